// round 16
// baseline (speedup 1.0000x reference)
#include <cuda_runtime.h>
#include <cuda_fp16.h>
#include <math.h>
#include <cstdint>

#define NN 50000
#define EE 800000
#define MM (EE + NN)
#define HH 8
#define FF 128
#define NBLK ((NN + 255) / 256)            // 196
#define GEMM_BM 64
#define GEMM_BLOCKS ((NN + GEMM_BM - 1) / GEMM_BM)    // 782
#define COUNT_BLOCKS ((MM + 128 * 4 - 1) / (128 * 4)) // 1661
#define FILL_BLOCKS ((MM + 1023) / 1024)              // 831

// ---------------- scratch (static __device__, no allocation) ----------------
__device__ __align__(16) float g_ha[NN * FF];   // post-GEMM h (fp32, gather stream)
__device__ __align__(16) float g_hb[NN * FF];   // post-aggregation h (layer output)
__device__ __align__(16) float g_es[NN * HH];
__device__ __align__(16) float g_ed[NN * HH];
__device__ int   g_src[MM];                     // src ids sorted by dst (CSR)
__device__ int   g_rowptr[NN + 1];
__device__ int   g_cnt[NN];
__device__ int   g_cur[NN];
__device__ volatile unsigned g_desc[NBLK];      // lookback descriptors
__device__ int   g_scan_done;                   // scan->fill flag
__device__ int   g_is64;                        // edge_index dtype flag

// fast ELU (expm1f is a costly accurate call; exp(x)-1 delta ~1e-7 abs)
__device__ __forceinline__ float elu_fast(float x) {
    return x > 0.f ? x : __expf(x) - 1.0f;
}

// ---------------- fused detect + zero ----------------
__global__ __launch_bounds__(256) void detzero_kernel(const void* __restrict__ ei) {
    int i = blockIdx.x * 256 + threadIdx.x;
    if (i < NN) g_cnt[i] = 0;
    if (i < NBLK) g_desc[i] = 0u;
    if (i == 0) g_scan_done = 0;
    if (blockIdx.x == 0 && threadIdx.x < 32) {
        long long v = ((const long long*)ei)[threadIdx.x];
        int bad = (v < 0 || v >= NN);
        unsigned m = __ballot_sync(0xffffffffu, bad);
        if (threadIdx.x == 0) g_is64 = (m == 0u);
    }
}

__device__ __forceinline__ int load_idx(const void* __restrict__ ei, int pos) {
    if (g_is64) return (int)((const long long*)ei)[pos];
    return ((const int*)ei)[pos];
}

// ---------------- HMMA GEMM body (BM=64, 128 threads, mma.sync m16n8k16) ----------------
// h = X@W, fp16 inputs, fp32 accumulate. Warp w computes rows [w*16, w*16+16)
// x all 128 cols: 16 n-tiles x 8 k-steps = 128 mma.sync.
// B (= fp16(W), col-major fragments) staged in smem with k-pairs interleaved
// so each B fragment is ONE conflict-free LDS.64:
//   slot(kk) = kk<8 ? (kk>>1)*4 + (kk&1) : ((kk-8)>>1)*4 + 2 + (kk&1)
// A fragments load straight from global (each X element read exactly once/CTA).
// Epilogue: accums -> smem (reusing B's storage) -> coalesced drain with
// per-row es/ed attention projections (no atomics).
__device__ void gemm_hmma_body(int block_m,
                               const float* __restrict__ X,
                               const float* __restrict__ W,
                               const float* __restrict__ asrc,
                               const float* __restrict__ adst) {
    __shared__ __align__(16) char smem_u[64 * 132 * 4];   // 33792 B
    __half* smB = (__half*)smem_u;                        // phase 1: 32768 B
    float* smOut = (float*)smem_u;                        // phase 2: 64x132 f32

    int tid = threadIdx.x;                 // 128 threads
    int wid = tid >> 5, lane = tid & 31;
    int g = lane >> 2, q = lane & 3;

    // ---- stage B = fp16(W[k][n]) in fragment-pair layout ----
    for (int i = tid; i < 128 * 128; i += 128) {
        int k = i >> 7, n = i & 127;
        int ks = k >> 4, kk = k & 15;
        int slot = (kk < 8) ? ((kk >> 1) * 4 + (kk & 1))
                            : (((kk - 8) >> 1) * 4 + 2 + (kk & 1));
        smB[ks * 2048 + n * 16 + slot] = __float2half_rn(W[i]);
    }

    // ---- preload all A fragments (rows wid*16+g and +8) ----
    int row0 = block_m + wid * 16 + g;
    int row8 = row0 + 8;
    bool v0 = row0 < NN, v8 = row8 < NN;
    const float* X0 = X + (size_t)row0 * FF;
    const float* X8 = X + (size_t)row8 * FF;
    uint32_t areg[8][4];
#pragma unroll
    for (int ks = 0; ks < 8; ks++) {
        int c = ks * 16 + 2 * q;
        float2 z = make_float2(0.f, 0.f);
        float2 f0 = v0 ? *(const float2*)(X0 + c) : z;
        float2 f1 = v8 ? *(const float2*)(X8 + c) : z;
        float2 f2 = v0 ? *(const float2*)(X0 + c + 8) : z;
        float2 f3 = v8 ? *(const float2*)(X8 + c + 8) : z;
        __half2 h;
        h = __floats2half2_rn(f0.x, f0.y); areg[ks][0] = *(uint32_t*)&h;
        h = __floats2half2_rn(f1.x, f1.y); areg[ks][1] = *(uint32_t*)&h;
        h = __floats2half2_rn(f2.x, f2.y); areg[ks][2] = *(uint32_t*)&h;
        h = __floats2half2_rn(f3.x, f3.y); areg[ks][3] = *(uint32_t*)&h;
    }
    __syncthreads();

    // ---- mainloop: 8 k-steps x 16 n-tiles ----
    float acc[16][4];
#pragma unroll
    for (int nt = 0; nt < 16; nt++)
#pragma unroll
        for (int j = 0; j < 4; j++) acc[nt][j] = 0.f;

#pragma unroll
    for (int ks = 0; ks < 8; ks++) {
#pragma unroll
        for (int nt = 0; nt < 16; nt++) {
            uint2 bb = *(const uint2*)(smB + ks * 2048 + (nt * 8 + g) * 16 + q * 4);
            asm volatile(
                "mma.sync.aligned.m16n8k16.row.col.f32.f16.f16.f32 "
                "{%0,%1,%2,%3}, {%4,%5,%6,%7}, {%8,%9}, {%0,%1,%2,%3};"
                : "+f"(acc[nt][0]), "+f"(acc[nt][1]), "+f"(acc[nt][2]), "+f"(acc[nt][3])
                : "r"(areg[ks][0]), "r"(areg[ks][1]), "r"(areg[ks][2]), "r"(areg[ks][3]),
                  "r"(bb.x), "r"(bb.y));
        }
    }
    __syncthreads();   // smB dead; reuse as smOut

    // ---- accum -> smOut (D frag: c0,c1 @ (g, 2q); c2,c3 @ (g+8, 2q)) ----
    {
        int r = wid * 16 + g;
#pragma unroll
        for (int nt = 0; nt < 16; nt++) {
            int cb = nt * 8 + 2 * q;
            *(float2*)&smOut[r * 132 + cb] = make_float2(acc[nt][0], acc[nt][1]);
            *(float2*)&smOut[(r + 8) * 132 + cb] = make_float2(acc[nt][2], acc[nt][3]);
        }
    }
    __syncthreads();

    // ---- drain: thread t -> row t>>1, half (t&1)*64 cols; es/ed per head ----
    int r = tid >> 1, half = tid & 1;
    int node = block_m + r;
    if (node < NN) {
        const float* rowp = smOut + r * 132 + half * 64;
        float4* dst = (float4*)(g_ha + (size_t)node * FF + half * 64);
#pragma unroll
        for (int hh = 0; hh < 4; hh++) {
            int head = half * 4 + hh;
            float es = 0.f, ed = 0.f;
#pragma unroll
            for (int qq = 0; qq < 4; qq++) {
                float4 v = *(const float4*)(rowp + hh * 16 + qq * 4);
                dst[hh * 4 + qq] = v;
                const float* as = asrc + head * 16 + qq * 4;
                const float* ad = adst + head * 16 + qq * 4;
                es += v.x * as[0] + v.y * as[1] + v.z * as[2] + v.w * as[3];
                ed += v.x * ad[0] + v.y * ad[1] + v.z * ad[2] + v.w * ad[3];
            }
            g_es[node * HH + head] = es;
            g_ed[node * HH + head] = ed;
        }
    }
}

// ---------------- fused: gemm layer 0 + edge count ----------------
__global__ __launch_bounds__(128)
void fused_gemm0_count_kernel(const float* __restrict__ x,
                              const float* __restrict__ W,
                              const float* __restrict__ asrc,
                              const float* __restrict__ adst,
                              const void* __restrict__ ei) {
    if (blockIdx.x < GEMM_BLOCKS) {
        gemm_hmma_body(blockIdx.x * GEMM_BM, x, W, asrc, adst);
    } else {
        int t = (blockIdx.x - GEMM_BLOCKS) * 128 + threadIdx.x;
#pragma unroll
        for (int j = 0; j < 4; j++) {
            int i = t * 4 + j;
            if (i < MM) {
                int dst = (i < EE) ? load_idx(ei, EE + i) : (i - EE);
                atomicAdd(&g_cnt[dst], 1);
            }
        }
    }
}

// ---------------- standalone GEMM (layers 1,2) ----------------
__global__ __launch_bounds__(128)
void gemm_attn_kernel(const float* __restrict__ W,
                      const float* __restrict__ asrc,
                      const float* __restrict__ adst) {
    gemm_hmma_body(blockIdx.x * GEMM_BM, g_hb, W, asrc, adst);
}

// ---------------- fused scan (decoupled lookback) + fill ----------------
__global__ __launch_bounds__(256) void scan_fill_kernel(const void* __restrict__ ei) {
    int tid = threadIdx.x, bid = blockIdx.x;
    if (bid < NBLK) {
        int gid = bid * 256 + tid;
        int v = (gid < NN) ? g_cnt[gid] : 0;
        int lane = tid & 31, w = tid >> 5;
        int x = v;
#pragma unroll
        for (int off = 1; off < 32; off <<= 1) {
            int y = __shfl_up_sync(0xffffffffu, x, off);
            if (lane >= off) x += y;
        }
        __shared__ int wsum[8];
        __shared__ int sh_pref;
        if (lane == 31) wsum[w] = x;
        __syncthreads();
        if (tid < 8) {
            int y = wsum[tid];
#pragma unroll
            for (int off = 1; off < 8; off <<= 1) {
                int z = __shfl_up_sync(0xffu, y, off);
                if (tid >= off) y += z;
            }
            wsum[tid] = y;
        }
        __syncthreads();
        int incl = x + (w > 0 ? wsum[w - 1] : 0);
        unsigned total = (unsigned)wsum[7];
        if (tid == 0) {
            int prefix = 0;
            if (bid == 0) {
                g_desc[0] = (2u << 30) | total;
            } else {
                g_desc[bid] = (1u << 30) | total;
                int p = bid - 1;
                while (true) {
                    unsigned dsc;
                    do { dsc = g_desc[p]; } while ((dsc >> 30) == 0u);
                    prefix += (int)(dsc & 0x3FFFFFFFu);
                    if ((dsc >> 30) == 2u) break;
                    p--;
                }
                g_desc[bid] = (2u << 30) | (unsigned)(prefix + (int)total);
            }
            sh_pref = prefix;
        }
        __syncthreads();
        int excl = incl - v + sh_pref;
        if (gid < NN) { g_rowptr[gid] = excl; g_cur[gid] = excl; }
        if (gid == 0) g_rowptr[NN] = MM;
        __syncthreads();
        if (tid == 0) {
            __threadfence();
            atomicAdd(&g_scan_done, 1);
        }
    } else {
        if (tid == 0) {
            while (*(volatile int*)&g_scan_done < NBLK) __nanosleep(64);
        }
        __syncthreads();
        int t = (bid - NBLK) * 256 + tid;
#pragma unroll
        for (int j = 0; j < 4; j++) {
            int i = t * 4 + j;
            if (i < MM) {
                int src, dst;
                if (i < EE) { src = load_idx(ei, i); dst = load_idx(ei, EE + i); }
                else        { src = dst = i - EE; }
                int pos = atomicAdd(&g_cur[dst], 1);
                g_src[pos] = src;
            }
        }
    }
}

// ---------------- fused softmax + weighted gather + bias + fast ELU ----------------
// One warp per destination node; 4-edge chunks with src prefetch (R14 structure).
__global__ __launch_bounds__(256)
void attn_agg_kernel(const float* __restrict__ bias) {
    int warp = blockIdx.x * 8 + (threadIdx.x >> 5);
    if (warp >= NN) return;
    int lane = threadIdx.x & 31;
    int h8 = lane & 7;
    int eslot = lane >> 3;      // 0..3
    int headq = lane >> 2;      // 0..7
    int lane4 = lane * 4;
    int r0 = g_rowptr[warp], r1 = g_rowptr[warp + 1];
    float edv = g_ed[warp * HH + h8];

    float d = 0.f;
    float4 acc = make_float4(0.f, 0.f, 0.f, 0.f);

    int e = r0;
    int end_full = r0 + ((r1 - r0) & ~3);
    int s_pf = (r0 + eslot < r1) ? g_src[r0 + eslot] : 0;

    for (; e < end_full; e += 4) {
        int s_cur = s_pf;
        int en = e + 4 + eslot;
        s_pf = (en < r1) ? g_src[en] : 0;

        float esv = __ldg(&g_es[s_cur * HH + h8]);

        int s0 = __shfl_sync(0xffffffffu, s_cur, 0);
        int s1 = __shfl_sync(0xffffffffu, s_cur, 8);
        int s2 = __shfl_sync(0xffffffffu, s_cur, 16);
        int s3 = __shfl_sync(0xffffffffu, s_cur, 24);
        float4 hv0 = *(const float4*)&g_ha[s0 * FF + lane4];
        float4 hv1 = *(const float4*)&g_ha[s1 * FF + lane4];
        float4 hv2 = *(const float4*)&g_ha[s2 * FF + lane4];
        float4 hv3 = *(const float4*)&g_ha[s3 * FF + lane4];

        float v = esv + edv;
        v = fmaxf(v, 0.2f * v);          // leaky_relu, exact for slope<1
        float w = __expf(v);
        d += w;

        float w0 = __shfl_sync(0xffffffffu, w, headq);
        float w1 = __shfl_sync(0xffffffffu, w, 8 + headq);
        float w2 = __shfl_sync(0xffffffffu, w, 16 + headq);
        float w3 = __shfl_sync(0xffffffffu, w, 24 + headq);

        acc.x += w0 * hv0.x; acc.y += w0 * hv0.y;
        acc.z += w0 * hv0.z; acc.w += w0 * hv0.w;
        acc.x += w1 * hv1.x; acc.y += w1 * hv1.y;
        acc.z += w1 * hv1.z; acc.w += w1 * hv1.w;
        acc.x += w2 * hv2.x; acc.y += w2 * hv2.y;
        acc.z += w2 * hv2.z; acc.w += w2 * hv2.w;
        acc.x += w3 * hv3.x; acc.y += w3 * hv3.y;
        acc.z += w3 * hv3.z; acc.w += w3 * hv3.w;
    }

    int rem = r1 - e;
    if (rem > 0) {
        int s_cur = s_pf;
        bool val = (eslot < rem);
        float esv = val ? __ldg(&g_es[s_cur * HH + h8]) : 0.f;
        float v = esv + edv;
        v = fmaxf(v, 0.2f * v);
        float w = val ? __expf(v) : 0.f;
        d += w;
#pragma unroll
        for (int j = 0; j < 3; j++) {
            if (j < rem) {
                int sj = __shfl_sync(0xffffffffu, s_cur, j * 8);
                float wq = __shfl_sync(0xffffffffu, w, j * 8 + headq);
                float4 hv = *(const float4*)&g_ha[sj * FF + lane4];
                acc.x += wq * hv.x; acc.y += wq * hv.y;
                acc.z += wq * hv.z; acc.w += wq * hv.w;
            }
        }
    }

    d += __shfl_xor_sync(0xffffffffu, d, 8);
    d += __shfl_xor_sync(0xffffffffu, d, 16);
    float dq = __shfl_sync(0xffffffffu, d, headq);
    float inv = 1.0f / (dq + 1e-16f);

    float4 b = *(const float4*)&bias[lane4];
    float4 o;
    o.x = elu_fast(acc.x * inv + b.x);
    o.y = elu_fast(acc.y * inv + b.y);
    o.z = elu_fast(acc.z * inv + b.z);
    o.w = elu_fast(acc.w * inv + b.w);
    *(float4*)&g_hb[warp * FF + lane4] = o;
}

// ---------------- final FC: out = h @ fc_w + fc_b  [N,16] ----------------
__global__ __launch_bounds__(256)
void final_fc_kernel(const float* __restrict__ fcw,
                     const float* __restrict__ fcb,
                     float* __restrict__ out) {
    int tid = blockIdx.x * blockDim.x + threadIdx.x;
    int node = tid >> 4;
    int c = tid & 15;
    if (node >= NN) return;
    const float* hr = g_hb + node * FF;
    float acc = fcb[c];
#pragma unroll 8
    for (int k = 0; k < FF; k++) acc += hr[k] * fcw[k * 16 + c];
    out[node * 16 + c] = acc;
}

// ---------------- launch ----------------
extern "C" void kernel_launch(void* const* d_in, const int* in_sizes, int n_in,
                              void* d_out, int out_size) {
    const float* x    = (const float*)d_in[0];
    const float* Ws   = (const float*)d_in[1];   // [3,128,128]
    const float* asrc = (const float*)d_in[2];   // [3,8,16]
    const float* adst = (const float*)d_in[3];
    const float* bias = (const float*)d_in[4];   // [3,128]
    const float* fcw  = (const float*)d_in[5];   // [128,16]
    const float* fcb  = (const float*)d_in[6];   // [16]
    const void*  ei   = (const void*)d_in[7];    // [2,E] int64 OR int32 (detected on device)
    float* out = (float*)d_out;

    int warp_blocks = (NN + 7) / 8;

    // launch index (ncu window = index 3):
    detzero_kernel<<<NBLK, 256>>>(ei);                                    // 0
    fused_gemm0_count_kernel<<<GEMM_BLOCKS + COUNT_BLOCKS, 128>>>(        // 1
        x, Ws, asrc, adst, ei);
    scan_fill_kernel<<<NBLK + FILL_BLOCKS, 256>>>(ei);                    // 2
    attn_agg_kernel<<<warp_blocks, 256>>>(bias);                          // 3 <- profiled

    for (int l = 1; l < 3; l++) {
        gemm_attn_kernel<<<GEMM_BLOCKS, 128>>>(Ws + l * 128 * 128,
                                               asrc + l * 128,
                                               adst + l * 128);
        attn_agg_kernel<<<warp_blocks, 256>>>(bias + l * 128);
    }

    final_fc_kernel<<<(NN * 16 + 255) / 256, 256>>>(fcw, fcb, out);
}

// round 17
// speedup vs baseline: 1.1137x; 1.1137x over previous
#include <cuda_runtime.h>
#include <cuda_fp16.h>
#include <math.h>
#include <cstdint>

#define NN 50000
#define EE 800000
#define MM (EE + NN)
#define HH 8
#define FF 128
#define NBLK ((NN + 255) / 256)            // 196
#define GEMM_BM 64
#define GEMM_BLOCKS ((NN + GEMM_BM - 1) / GEMM_BM)    // 782
#define COUNT_BLOCKS ((MM + 128 * 4 - 1) / (128 * 4)) // 1661
#define FILL_BLOCKS ((MM + 1023) / 1024)              // 831

// ---------------- scratch (static __device__, no allocation) ----------------
__device__ __align__(16) __half g_hh[NN * FF];  // post-GEMM h (fp16 gather stream)
__device__ __align__(16) float g_hb[NN * FF];   // post-aggregation h (layer output)
__device__ __align__(16) float g_es[NN * HH];
__device__ __align__(16) float g_ed[NN * HH];
__device__ int   g_src[MM];                     // src ids sorted by dst (CSR)
__device__ int   g_rowptr[NN + 1];
__device__ int   g_cnt[NN];
__device__ int   g_cur[NN];
__device__ volatile unsigned g_desc[NBLK];      // lookback descriptors
__device__ int   g_scan_done;                   // scan->fill flag
__device__ int   g_is64;                        // edge_index dtype flag

// ---------------- packed f32x2 helpers ----------------
__device__ __forceinline__ unsigned long long pack2s(float x) {
    unsigned long long r;
    asm("mov.b64 %0, {%1, %1};" : "=l"(r) : "f"(x));
    return r;
}
__device__ __forceinline__ void fma2(unsigned long long& acc,
                                     unsigned long long a, unsigned long long b) {
    asm("fma.rn.f32x2 %0, %1, %2, %0;" : "+l"(acc) : "l"(a), "l"(b));
}
__device__ __forceinline__ float2 unpack2(unsigned long long v) {
    float2 f;
    asm("mov.b64 {%0, %1}, %2;" : "=f"(f.x), "=f"(f.y) : "l"(v));
    return f;
}

// fast ELU (expm1f is a costly accurate call; exp(x)-1 delta ~1e-7 abs)
__device__ __forceinline__ float elu_fast(float x) {
    return x > 0.f ? x : __expf(x) - 1.0f;
}

// ---------------- fused detect + zero ----------------
__global__ __launch_bounds__(256) void detzero_kernel(const void* __restrict__ ei) {
    int i = blockIdx.x * 256 + threadIdx.x;
    if (i < NN) g_cnt[i] = 0;
    if (i < NBLK) g_desc[i] = 0u;
    if (i == 0) g_scan_done = 0;
    if (blockIdx.x == 0 && threadIdx.x < 32) {
        long long v = ((const long long*)ei)[threadIdx.x];
        int bad = (v < 0 || v >= NN);
        unsigned m = __ballot_sync(0xffffffffu, bad);
        if (threadIdx.x == 0) g_is64 = (m == 0u);
    }
}

__device__ __forceinline__ int load_idx(const void* __restrict__ ei, int pos) {
    if (g_is64) return (int)((const long long*)ei)[pos];
    return ((const int*)ei)[pos];
}

// ---------------- GEMM body (BM=64, 128 threads, 8x8 tile, FFMA2) ----------------
__device__ __forceinline__ void gemm_body(int block_m,
                                          const float* __restrict__ X,
                                          const float* __restrict__ W,
                                          const float* __restrict__ asrc,
                                          const float* __restrict__ adst) {
    __shared__ float Xs[16][GEMM_BM + 4];   // [16][68], rows 16B-aligned
    __shared__ float Ws_s[16][128];
    __shared__ float es_sh[GEMM_BM][HH];
    __shared__ float ed_sh[GEMM_BM][HH];

    int tid = threadIdx.x;                  // 128 threads

    for (int i = tid; i < GEMM_BM * HH; i += 128) {
        (&es_sh[0][0])[i] = 0.0f;
        (&ed_sh[0][0])[i] = 0.0f;
    }

    int tm = tid >> 4;   // 0..7 -> rows tm*8..+7
    int tn = tid & 15;   // cols tn*8..+7

    unsigned long long accp[8][4];
#pragma unroll
    for (int i = 0; i < 8; i++)
#pragma unroll
        for (int j = 0; j < 4; j++) accp[i][j] = 0ull;

    int ch0 = 2 * tn, ch1 = 2 * tn + 1;
    int p0 = (ch0 ^ ((ch0 >> 3) & 1)) * 4;
    int p1 = (ch1 ^ ((ch1 >> 3) & 1)) * 4;

    for (int k0 = 0; k0 < FF; k0 += 16) {
        // W tile 16x128 (swizzled chunks)
#pragma unroll
        for (int i = 0; i < 4; i++) {
            int idx = (tid + i * 128) * 4;       // 0..2044
            int kk = idx >> 7, cc = idx & 127;
            float4 v = *(const float4*)&W[(k0 + kk) * 128 + cc];
            int ch = cc >> 2;
            int phys = (ch ^ ((ch >> 3) & 1)) * 4;
            *(float4*)&Ws_s[kk][phys] = v;
        }
        // X tile 64x16 (transposed store)
#pragma unroll
        for (int i = 0; i < 2; i++) {
            int idx = (tid + i * 128) * 4;       // 0..1020
            int m = idx >> 4, kk = idx & 15;
            int node = block_m + m;
            float4 v = make_float4(0.f, 0.f, 0.f, 0.f);
            if (node < NN) v = *(const float4*)&X[node * FF + k0 + kk];
            Xs[kk + 0][m] = v.x; Xs[kk + 1][m] = v.y;
            Xs[kk + 2][m] = v.z; Xs[kk + 3][m] = v.w;
        }
        __syncthreads();
#pragma unroll
        for (int k = 0; k < 16; k++) {
            const unsigned long long* bp0 = (const unsigned long long*)&Ws_s[k][p0];
            const unsigned long long* bp1 = (const unsigned long long*)&Ws_s[k][p1];
            unsigned long long b0 = bp0[0], b1 = bp0[1];
            unsigned long long b2 = bp1[0], b3 = bp1[1];
            float4 a03 = *(const float4*)&Xs[k][tm * 8];
            float4 a47 = *(const float4*)&Xs[k][tm * 8 + 4];
            unsigned long long ap[8];
            ap[0] = pack2s(a03.x); ap[1] = pack2s(a03.y);
            ap[2] = pack2s(a03.z); ap[3] = pack2s(a03.w);
            ap[4] = pack2s(a47.x); ap[5] = pack2s(a47.y);
            ap[6] = pack2s(a47.z); ap[7] = pack2s(a47.w);
#pragma unroll
            for (int i = 0; i < 8; i++) {
                fma2(accp[i][0], ap[i], b0); fma2(accp[i][1], ap[i], b1);
                fma2(accp[i][2], ap[i], b2); fma2(accp[i][3], ap[i], b3);
            }
        }
        __syncthreads();
    }

    // epilogue: store h (fp16 pack, fp32 compute), attention projections fp32
    int h = tn >> 1;
    float as_[8], ad_[8];
#pragma unroll
    for (int j = 0; j < 8; j++) {
        int c = (tn * 8 + j) & 15;
        as_[j] = asrc[h * 16 + c];
        ad_[j] = adst[h * 16 + c];
    }
#pragma unroll
    for (int i = 0; i < 8; i++) {
        int m = tm * 8 + i;
        int node = block_m + m;
        if (node < NN) {
            float2 c0 = unpack2(accp[i][0]);
            float2 c1 = unpack2(accp[i][1]);
            float2 c2 = unpack2(accp[i][2]);
            float2 c3 = unpack2(accp[i][3]);
            float accv[8] = {c0.x, c0.y, c1.x, c1.y, c2.x, c2.y, c3.x, c3.y};
            uint4 hp;
            __half2 h0 = __floats2half2_rn(accv[0], accv[1]);
            __half2 h1 = __floats2half2_rn(accv[2], accv[3]);
            __half2 h2 = __floats2half2_rn(accv[4], accv[5]);
            __half2 h3 = __floats2half2_rn(accv[6], accv[7]);
            hp.x = *(uint32_t*)&h0; hp.y = *(uint32_t*)&h1;
            hp.z = *(uint32_t*)&h2; hp.w = *(uint32_t*)&h3;
            *(uint4*)&g_hh[node * FF + tn * 8] = hp;
            float ps = 0.f, pd = 0.f;
#pragma unroll
            for (int j = 0; j < 8; j++) { ps += accv[j] * as_[j]; pd += accv[j] * ad_[j]; }
            atomicAdd(&es_sh[m][h], ps);
            atomicAdd(&ed_sh[m][h], pd);
        }
    }
    __syncthreads();
    for (int i = tid; i < GEMM_BM * HH; i += 128) {
        int node = block_m + (i >> 3);
        if (node < NN) {
            g_es[node * HH + (i & 7)] = (&es_sh[0][0])[i];
            g_ed[node * HH + (i & 7)] = (&ed_sh[0][0])[i];
        }
    }
}

// ---------------- fused: gemm layer 0 + edge count ----------------
__global__ __launch_bounds__(128, 4)
void fused_gemm0_count_kernel(const float* __restrict__ x,
                              const float* __restrict__ W,
                              const float* __restrict__ asrc,
                              const float* __restrict__ adst,
                              const void* __restrict__ ei) {
    if (blockIdx.x < GEMM_BLOCKS) {
        gemm_body(blockIdx.x * GEMM_BM, x, W, asrc, adst);
    } else {
        int t = (blockIdx.x - GEMM_BLOCKS) * 128 + threadIdx.x;
#pragma unroll
        for (int j = 0; j < 4; j++) {
            int i = t * 4 + j;
            if (i < MM) {
                int dst = (i < EE) ? load_idx(ei, EE + i) : (i - EE);
                atomicAdd(&g_cnt[dst], 1);
            }
        }
    }
}

// ---------------- standalone GEMM (layers 1,2) ----------------
__global__ __launch_bounds__(128, 4)
void gemm_attn_kernel(const float* __restrict__ W,
                      const float* __restrict__ asrc,
                      const float* __restrict__ adst) {
    gemm_body(blockIdx.x * GEMM_BM, g_hb, W, asrc, adst);
}

// ---------------- fused scan (decoupled lookback) + fill ----------------
__global__ __launch_bounds__(256) void scan_fill_kernel(const void* __restrict__ ei) {
    int tid = threadIdx.x, bid = blockIdx.x;
    if (bid < NBLK) {
        int gid = bid * 256 + tid;
        int v = (gid < NN) ? g_cnt[gid] : 0;
        int lane = tid & 31, w = tid >> 5;
        int x = v;
#pragma unroll
        for (int off = 1; off < 32; off <<= 1) {
            int y = __shfl_up_sync(0xffffffffu, x, off);
            if (lane >= off) x += y;
        }
        __shared__ int wsum[8];
        __shared__ int sh_pref;
        if (lane == 31) wsum[w] = x;
        __syncthreads();
        if (tid < 8) {
            int y = wsum[tid];
#pragma unroll
            for (int off = 1; off < 8; off <<= 1) {
                int z = __shfl_up_sync(0xffu, y, off);
                if (tid >= off) y += z;
            }
            wsum[tid] = y;
        }
        __syncthreads();
        int incl = x + (w > 0 ? wsum[w - 1] : 0);
        unsigned total = (unsigned)wsum[7];
        if (tid == 0) {
            int prefix = 0;
            if (bid == 0) {
                g_desc[0] = (2u << 30) | total;
            } else {
                g_desc[bid] = (1u << 30) | total;
                int p = bid - 1;
                while (true) {
                    unsigned dsc;
                    do { dsc = g_desc[p]; } while ((dsc >> 30) == 0u);
                    prefix += (int)(dsc & 0x3FFFFFFFu);
                    if ((dsc >> 30) == 2u) break;
                    p--;
                }
                g_desc[bid] = (2u << 30) | (unsigned)(prefix + (int)total);
            }
            sh_pref = prefix;
        }
        __syncthreads();
        int excl = incl - v + sh_pref;
        if (gid < NN) { g_rowptr[gid] = excl; g_cur[gid] = excl; }
        if (gid == 0) g_rowptr[NN] = MM;
        __syncthreads();
        if (tid == 0) {
            __threadfence();
            atomicAdd(&g_scan_done, 1);
        }
    } else {
        if (tid == 0) {
            while (*(volatile int*)&g_scan_done < NBLK) __nanosleep(64);
        }
        __syncthreads();
        int t = (bid - NBLK) * 256 + tid;
#pragma unroll
        for (int j = 0; j < 4; j++) {
            int i = t * 4 + j;
            if (i < MM) {
                int src, dst;
                if (i < EE) { src = load_idx(ei, i); dst = load_idx(ei, EE + i); }
                else        { src = dst = i - EE; }
                int pos = atomicAdd(&g_cur[dst], 1);
                g_src[pos] = src;
            }
        }
    }
}

// ---------------- fused softmax + weighted gather (fp16) + bias + fast ELU ----------------
// One warp per destination node; 4-edge chunks with src prefetch (R14 structure),
// h gathered as fp16 (256B/edge instead of 512B).
__global__ __launch_bounds__(256)
void attn_agg_kernel(const float* __restrict__ bias) {
    int warp = blockIdx.x * 8 + (threadIdx.x >> 5);
    if (warp >= NN) return;
    int lane = threadIdx.x & 31;
    int h8 = lane & 7;
    int eslot = lane >> 3;      // 0..3
    int headq = lane >> 2;      // 0..7
    int lane4 = lane * 4;
    int r0 = g_rowptr[warp], r1 = g_rowptr[warp + 1];
    float edv = g_ed[warp * HH + h8];

    float d = 0.f;
    float4 acc = make_float4(0.f, 0.f, 0.f, 0.f);

    int e = r0;
    int end_full = r0 + ((r1 - r0) & ~3);
    int s_pf = (r0 + eslot < r1) ? g_src[r0 + eslot] : 0;

    for (; e < end_full; e += 4) {
        int s_cur = s_pf;
        int en = e + 4 + eslot;
        s_pf = (en < r1) ? g_src[en] : 0;

        float esv = __ldg(&g_es[s_cur * HH + h8]);

        int s0 = __shfl_sync(0xffffffffu, s_cur, 0);
        int s1 = __shfl_sync(0xffffffffu, s_cur, 8);
        int s2 = __shfl_sync(0xffffffffu, s_cur, 16);
        int s3 = __shfl_sync(0xffffffffu, s_cur, 24);
        uint2 hr0 = *(const uint2*)&g_hh[s0 * FF + lane4];
        uint2 hr1 = *(const uint2*)&g_hh[s1 * FF + lane4];
        uint2 hr2 = *(const uint2*)&g_hh[s2 * FF + lane4];
        uint2 hr3 = *(const uint2*)&g_hh[s3 * FF + lane4];

        float v = esv + edv;
        v = fmaxf(v, 0.2f * v);          // leaky_relu, exact for slope<1
        float w = __expf(v);
        d += w;

        float w0 = __shfl_sync(0xffffffffu, w, headq);
        float w1 = __shfl_sync(0xffffffffu, w, 8 + headq);
        float w2 = __shfl_sync(0xffffffffu, w, 16 + headq);
        float w3 = __shfl_sync(0xffffffffu, w, 24 + headq);

        float2 a0 = __half22float2(*(const __half2*)&hr0.x);
        float2 b0 = __half22float2(*(const __half2*)&hr0.y);
        acc.x += w0 * a0.x; acc.y += w0 * a0.y;
        acc.z += w0 * b0.x; acc.w += w0 * b0.y;
        float2 a1 = __half22float2(*(const __half2*)&hr1.x);
        float2 b1 = __half22float2(*(const __half2*)&hr1.y);
        acc.x += w1 * a1.x; acc.y += w1 * a1.y;
        acc.z += w1 * b1.x; acc.w += w1 * b1.y;
        float2 a2 = __half22float2(*(const __half2*)&hr2.x);
        float2 b2 = __half22float2(*(const __half2*)&hr2.y);
        acc.x += w2 * a2.x; acc.y += w2 * a2.y;
        acc.z += w2 * b2.x; acc.w += w2 * b2.y;
        float2 a3 = __half22float2(*(const __half2*)&hr3.x);
        float2 b3 = __half22float2(*(const __half2*)&hr3.y);
        acc.x += w3 * a3.x; acc.y += w3 * a3.y;
        acc.z += w3 * b3.x; acc.w += w3 * b3.y;
    }

    int rem = r1 - e;
    if (rem > 0) {
        int s_cur = s_pf;
        bool val = (eslot < rem);
        float esv = val ? __ldg(&g_es[s_cur * HH + h8]) : 0.f;
        float v = esv + edv;
        v = fmaxf(v, 0.2f * v);
        float w = val ? __expf(v) : 0.f;
        d += w;
#pragma unroll
        for (int j = 0; j < 3; j++) {
            if (j < rem) {
                int sj = __shfl_sync(0xffffffffu, s_cur, j * 8);
                float wq = __shfl_sync(0xffffffffu, w, j * 8 + headq);
                uint2 hr = *(const uint2*)&g_hh[sj * FF + lane4];
                float2 fa = __half22float2(*(const __half2*)&hr.x);
                float2 fb = __half22float2(*(const __half2*)&hr.y);
                acc.x += wq * fa.x; acc.y += wq * fa.y;
                acc.z += wq * fb.x; acc.w += wq * fb.y;
            }
        }
    }

    d += __shfl_xor_sync(0xffffffffu, d, 8);
    d += __shfl_xor_sync(0xffffffffu, d, 16);
    float dq = __shfl_sync(0xffffffffu, d, headq);
    float inv = 1.0f / (dq + 1e-16f);

    float4 b = *(const float4*)&bias[lane4];
    float4 o;
    o.x = elu_fast(acc.x * inv + b.x);
    o.y = elu_fast(acc.y * inv + b.y);
    o.z = elu_fast(acc.z * inv + b.z);
    o.w = elu_fast(acc.w * inv + b.w);
    *(float4*)&g_hb[warp * FF + lane4] = o;
}

// ---------------- final FC: out = h @ fc_w + fc_b  [N,16] ----------------
__global__ __launch_bounds__(256)
void final_fc_kernel(const float* __restrict__ fcw,
                     const float* __restrict__ fcb,
                     float* __restrict__ out) {
    int tid = blockIdx.x * blockDim.x + threadIdx.x;
    int node = tid >> 4;
    int c = tid & 15;
    if (node >= NN) return;
    const float* hr = g_hb + node * FF;
    float acc = fcb[c];
#pragma unroll 8
    for (int k = 0; k < FF; k++) acc += hr[k] * fcw[k * 16 + c];
    out[node * 16 + c] = acc;
}

// ---------------- launch ----------------
extern "C" void kernel_launch(void* const* d_in, const int* in_sizes, int n_in,
                              void* d_out, int out_size) {
    const float* x    = (const float*)d_in[0];
    const float* Ws   = (const float*)d_in[1];   // [3,128,128]
    const float* asrc = (const float*)d_in[2];   // [3,8,16]
    const float* adst = (const float*)d_in[3];
    const float* bias = (const float*)d_in[4];   // [3,128]
    const float* fcw  = (const float*)d_in[5];   // [128,16]
    const float* fcb  = (const float*)d_in[6];   // [16]
    const void*  ei   = (const void*)d_in[7];    // [2,E] int64 OR int32 (detected on device)
    float* out = (float*)d_out;

    int warp_blocks = (NN + 7) / 8;

    // launch index (ncu window = index 3):
    detzero_kernel<<<NBLK, 256>>>(ei);                                    // 0
    fused_gemm0_count_kernel<<<GEMM_BLOCKS + COUNT_BLOCKS, 128>>>(        // 1
        x, Ws, asrc, adst, ei);
    scan_fill_kernel<<<NBLK + FILL_BLOCKS, 256>>>(ei);                    // 2
    attn_agg_kernel<<<warp_blocks, 256>>>(bias);                          // 3 <- profiled

    for (int l = 1; l < 3; l++) {
        gemm_attn_kernel<<<GEMM_BLOCKS, 128>>>(Ws + l * 128 * 128,
                                               asrc + l * 128,
                                               adst + l * 128);
        attn_agg_kernel<<<warp_blocks, 256>>>(bias + l * 128);
    }

    final_fc_kernel<<<(NN * 16 + 255) / 256, 256>>>(fcw, fcb, out);
}